// round 13
// baseline (speedup 1.0000x reference)
#include <cuda_runtime.h>

#define N_NODES 100000
#define N_EDGES 1600000
#define D 128
#define BN_EPS 1e-5f
#define LEAKY 0.01f

typedef unsigned long long u64;

#define PACK2(dst, lo, hi) \
    asm("mov.b64 %0, {%1, %2};" : "=l"(dst) : "f"(lo), "f"(hi))
#define UNPACK2(lo, hi, src) \
    asm("mov.b64 {%0, %1}, %2;" : "=f"(lo), "=f"(hi) : "l"(src))
#define FFMA2(d, a, b, c) \
    asm("fma.rn.f32x2 %0, %1, %2, %3;" : "=l"(d) : "l"(a), "l"(b), "l"(c))

// ---------------- device scratch (no allocation allowed) ----------------
__device__ int   g_outdeg[N_NODES];
__device__ int   g_indeg [N_NODES];
__device__ int   g_off   [N_NODES];
__device__ int   g_cur   [N_NODES];
__device__ int   g_col   [N_EDGES];
__device__ float g_nsrc  [N_NODES];
__device__ float g_ndst  [N_NODES];
__device__ float g_m     [N_NODES * D];   // aggregation output
__device__ float g_h     [N_NODES * D];   // layer-0 activation

#define SB 512
#define NSB ((N_NODES + SB - 1) / SB)     // 196 scan blocks
__device__ int g_blocksum[NSB];
__device__ int g_blockoff[256];

// ---------------- prep kernels ----------------
__global__ void zero_deg_kernel() {
    int i = blockIdx.x * blockDim.x + threadIdx.x;
    if (i < N_NODES) { g_outdeg[i] = 0; g_indeg[i] = 0; }
}

__global__ void degree_kernel(const int* __restrict__ src, const int* __restrict__ dst) {
    int e = blockIdx.x * blockDim.x + threadIdx.x;
    if (e < N_EDGES) {
        atomicAdd(&g_outdeg[src[e]], 1);
        atomicAdd(&g_indeg [dst[e]], 1);
    }
}

__global__ void norm_kernel() {
    int i = blockIdx.x * blockDim.x + threadIdx.x;
    if (i < N_NODES) {
        // +1 for the self loop; degrees are then always >= 1
        g_nsrc[i] = rsqrtf((float)(g_outdeg[i] + 1));
        g_ndst[i] = rsqrtf((float)(g_indeg [i] + 1));
    }
}

// ---------------- two-level scan of g_indeg -> g_off / g_cur ----------------
__global__ void __launch_bounds__(SB) blocksum_kernel() {
    __shared__ int sh[SB];
    int t = threadIdx.x;
    int i = blockIdx.x * SB + t;
    sh[t] = (i < N_NODES) ? g_indeg[i] : 0;
    __syncthreads();
#pragma unroll
    for (int off = SB / 2; off > 0; off >>= 1) {
        if (t < off) sh[t] += sh[t + off];
        __syncthreads();
    }
    if (t == 0) g_blocksum[blockIdx.x] = sh[0];
}

__global__ void __launch_bounds__(256) blockscan_kernel() {
    __shared__ int sh[256];
    int t = threadIdx.x;
    int v = (t < NSB) ? g_blocksum[t] : 0;
    sh[t] = v;
    __syncthreads();
#pragma unroll
    for (int off = 1; off < 256; off <<= 1) {
        int u = (t >= off) ? sh[t - off] : 0;
        __syncthreads();
        sh[t] += u;
        __syncthreads();
    }
    g_blockoff[t] = sh[t] - v;   // exclusive prefix of block sums
}

__global__ void __launch_bounds__(SB) offsets_kernel() {
    __shared__ int sh[SB];
    int t = threadIdx.x;
    int i = blockIdx.x * SB + t;
    int v = (i < N_NODES) ? g_indeg[i] : 0;
    sh[t] = v;
    __syncthreads();
#pragma unroll
    for (int off = 1; off < SB; off <<= 1) {
        int u = (t >= off) ? sh[t - off] : 0;
        __syncthreads();
        sh[t] += u;
        __syncthreads();
    }
    if (i < N_NODES) {
        int o = g_blockoff[blockIdx.x] + sh[t] - v;   // global exclusive prefix
        g_off[i] = o;
        g_cur[i] = o;
    }
}

__global__ void scatter_kernel(const int* __restrict__ src, const int* __restrict__ dst) {
    int e = blockIdx.x * blockDim.x + threadIdx.x;
    if (e < N_EDGES) {
        int p = atomicAdd(&g_cur[dst[e]], 1);
        g_col[p] = src[e];
    }
}

// ---------------- aggregation: m[i] = ndst[i] * ( nsrc[i]*h[i] + sum_{s in N(i)} nsrc[s]*h[s] )
__global__ void __launch_bounds__(128) agg_kernel(const float* __restrict__ hin,
                                                  float* __restrict__ hout) {
    int node = blockIdx.x;
    int c    = threadIdx.x;
    float acc = hin[node * D + c] * g_nsrc[node];   // self loop
    int beg = g_off[node];
    int cnt = g_indeg[node];
    int k = 0;
    for (; k + 4 <= cnt; k += 4) {
        int s0 = __ldg(&g_col[beg + k + 0]);
        int s1 = __ldg(&g_col[beg + k + 1]);
        int s2 = __ldg(&g_col[beg + k + 2]);
        int s3 = __ldg(&g_col[beg + k + 3]);
        float n0 = __ldg(&g_nsrc[s0]);
        float n1 = __ldg(&g_nsrc[s1]);
        float n2 = __ldg(&g_nsrc[s2]);
        float n3 = __ldg(&g_nsrc[s3]);
        float v0 = __ldg(&hin[s0 * D + c]);
        float v1 = __ldg(&hin[s1 * D + c]);
        float v2 = __ldg(&hin[s2 * D + c]);
        float v3 = __ldg(&hin[s3 * D + c]);
        acc += n0 * v0;
        acc += n1 * v1;
        acc += n2 * v2;
        acc += n3 * v3;
    }
    for (; k < cnt; k++) {
        int s = __ldg(&g_col[beg + k]);
        acc += __ldg(&g_nsrc[s]) * __ldg(&hin[s * D + c]);
    }
    hout[node * D + c] = acc * g_ndst[node];
}

// ---------------- GEMM (+optional BN/leaky): out = M @ W + b ----------------
// block = 128 threads = 4 warps; warp w handles rows [w*8, w*8+8) of a 32-row tile;
// lane l owns cols 4l..4l+3 as two f32x2 pairs. W staged in smem as floats
// (LDS.128 per k gives two ready-made column pairs); the m-tile is staged
// pre-duplicated ((v,v) u64 words) so the broadcast multiplier is one LDS.64.
#define RTILE 32
#define RW 8
#define GEMM_GRID 296   // 2 blocks per SM (96 KB smem each)

template <bool FUSE_BN>
__global__ void __launch_bounds__(128) gemm_kernel(
    const float* __restrict__ M, const float* __restrict__ W,
    const float* __restrict__ bias,
    const float* __restrict__ gamma, const float* __restrict__ beta,
    const float* __restrict__ mean,  const float* __restrict__ var,
    float* __restrict__ out) {
    extern __shared__ float smem[];
    float* Ws  = smem;                    // 128*128 floats = 64 KB
    u64*   ms2 = (u64*)(smem + D * D);    // RTILE*128 duplicated pairs = 32 KB

    int tid  = threadIdx.x;
    int warp = tid >> 5;
    int lane = tid & 31;

    for (int i = tid; i < D * D; i += 128) Ws[i] = W[i];

    float4 bi = ((const float4*)bias)[lane];
    u64 bi01, bi23;
    PACK2(bi01, bi.x, bi.y);
    PACK2(bi23, bi.z, bi.w);

    float4 sc = make_float4(0.f, 0.f, 0.f, 0.f);
    float4 sh = make_float4(0.f, 0.f, 0.f, 0.f);
    if (FUSE_BN) {
        float4 g  = ((const float4*)gamma)[lane];
        float4 be = ((const float4*)beta )[lane];
        float4 mu = ((const float4*)mean )[lane];
        float4 va = ((const float4*)var  )[lane];
        sc.x = g.x * rsqrtf(va.x + BN_EPS); sh.x = be.x - mu.x * sc.x;
        sc.y = g.y * rsqrtf(va.y + BN_EPS); sh.y = be.y - mu.y * sc.y;
        sc.z = g.z * rsqrtf(va.z + BN_EPS); sh.z = be.z - mu.z * sc.z;
        sc.w = g.w * rsqrtf(va.w + BN_EPS); sh.w = be.w - mu.w * sc.w;
    }
    __syncthreads();

    // N_NODES = 3125 * RTILE exactly -> no row tail handling needed
    for (int row0 = blockIdx.x * RTILE; row0 < N_NODES; row0 += gridDim.x * RTILE) {
        for (int i = tid; i < RTILE * D; i += 128) {
            float v = M[row0 * D + i];
            u64 p;
            PACK2(p, v, v);
            ms2[i] = p;
        }
        __syncthreads();

        u64 a01[RW], a23[RW];
#pragma unroll
        for (int r = 0; r < RW; r++) { a01[r] = bi01; a23[r] = bi23; }

#pragma unroll 4
        for (int kk = 0; kk < D; kk++) {
            ulonglong2 w = *(const ulonglong2*)&Ws[kk * D + 4 * lane];
#pragma unroll
            for (int r = 0; r < RW; r++) {
                u64 mvv = ms2[(warp * RW + r) * D + kk];
                FFMA2(a01[r], mvv, w.x, a01[r]);
                FFMA2(a23[r], mvv, w.y, a23[r]);
            }
        }

#pragma unroll
        for (int r = 0; r < RW; r++) {
            int row = row0 + warp * RW + r;
            float4 v;
            UNPACK2(v.x, v.y, a01[r]);
            UNPACK2(v.z, v.w, a23[r]);
            if (FUSE_BN) {
                v.x = v.x * sc.x + sh.x; v.x = v.x > 0.f ? v.x : LEAKY * v.x;
                v.y = v.y * sc.y + sh.y; v.y = v.y > 0.f ? v.y : LEAKY * v.y;
                v.z = v.z * sc.z + sh.z; v.z = v.z > 0.f ? v.z : LEAKY * v.z;
                v.w = v.w * sc.w + sh.w; v.w = v.w > 0.f ? v.w : LEAKY * v.w;
            }
            *(float4*)&out[row * D + 4 * lane] = v;
        }
        __syncthreads();
    }
}

// ---------------- launch ----------------
extern "C" void kernel_launch(void* const* d_in, const int* in_sizes, int n_in,
                              void* d_out, int out_size) {
    const float* x     = (const float*)d_in[0];
    const int*   src   = (const int*)  d_in[1];
    const int*   dst   = (const int*)  d_in[2];
    const float* W1    = (const float*)d_in[3];
    const float* b1    = (const float*)d_in[4];
    const float* W2    = (const float*)d_in[5];
    const float* b2    = (const float*)d_in[6];
    const float* gamma = (const float*)d_in[7];
    const float* beta  = (const float*)d_in[8];
    const float* rmean = (const float*)d_in[9];
    const float* rvar  = (const float*)d_in[10];
    float* out = (float*)d_out;

    const int gemm_smem = (D * D) * (int)sizeof(float) + RTILE * D * (int)sizeof(u64);  // 96 KB
    cudaFuncSetAttribute(gemm_kernel<true>,
                         cudaFuncAttributeMaxDynamicSharedMemorySize, gemm_smem);
    cudaFuncSetAttribute(gemm_kernel<false>,
                         cudaFuncAttributeMaxDynamicSharedMemorySize, gemm_smem);

    float* d_m = nullptr;
    float* d_h = nullptr;
    cudaGetSymbolAddress((void**)&d_m, g_m);
    cudaGetSymbolAddress((void**)&d_h, g_h);

    const int nodeGrid = (N_NODES + 255) / 256;
    const int edgeGrid = (N_EDGES + 255) / 256;

    // graph prep (rebuilt every replay; degrees/cursors reset each time)
    zero_deg_kernel<<<nodeGrid, 256>>>();
    degree_kernel<<<edgeGrid, 256>>>(src, dst);
    norm_kernel<<<nodeGrid, 256>>>();
    blocksum_kernel<<<NSB, SB>>>();
    blockscan_kernel<<<1, 256>>>();
    offsets_kernel<<<NSB, SB>>>();
    scatter_kernel<<<edgeGrid, 256>>>(src, dst);

    // layer 0: conv -> BN(eval) -> leaky
    agg_kernel<<<N_NODES, 128>>>(x, d_m);
    gemm_kernel<true><<<GEMM_GRID, 128, gemm_smem>>>(d_m, W1, b1, gamma, beta,
                                                     rmean, rvar, d_h);

    // layer 1: conv only
    agg_kernel<<<N_NODES, 128>>>(d_h, d_m);
    gemm_kernel<false><<<GEMM_GRID, 128, gemm_smem>>>(d_m, W2, b2, nullptr, nullptr,
                                                      nullptr, nullptr, out);
}

// round 17
// speedup vs baseline: 1.2460x; 1.2460x over previous
#include <cuda_runtime.h>
#include <cstdint>

#define N_NODES 100000
#define N_EDGES 1600000
#define D 128
#define BN_EPS 1e-5f
#define LEAKY 0.01f

// ---------------- device scratch (no allocation allowed) ----------------
__device__ int   g_outdeg[N_NODES];
__device__ int   g_indeg [N_NODES];
__device__ int   g_off   [N_NODES];
__device__ int   g_cur   [N_NODES];
__device__ int   g_col   [N_EDGES];
__device__ float g_nsrc  [N_NODES];
__device__ float g_ndst  [N_NODES];
__device__ float g_m     [N_NODES * D];   // aggregation output
__device__ float g_h     [N_NODES * D];   // layer-0 activation

#define SB 512
#define NSB ((N_NODES + SB - 1) / SB)     // 196 scan blocks
__device__ int g_blocksum[NSB];
__device__ int g_blockoff[256];

// ---------------- prep kernels ----------------
__global__ void zero_deg_kernel() {
    int i = blockIdx.x * blockDim.x + threadIdx.x;
    if (i < N_NODES) { g_outdeg[i] = 0; g_indeg[i] = 0; }
}

__global__ void degree_kernel(const int* __restrict__ src, const int* __restrict__ dst) {
    int e = blockIdx.x * blockDim.x + threadIdx.x;
    if (e < N_EDGES) {
        atomicAdd(&g_outdeg[src[e]], 1);
        atomicAdd(&g_indeg [dst[e]], 1);
    }
}

__global__ void norm_kernel() {
    int i = blockIdx.x * blockDim.x + threadIdx.x;
    if (i < N_NODES) {
        g_nsrc[i] = rsqrtf((float)(g_outdeg[i] + 1));
        g_ndst[i] = rsqrtf((float)(g_indeg [i] + 1));
    }
}

__global__ void __launch_bounds__(SB) blocksum_kernel() {
    __shared__ int sh[SB];
    int t = threadIdx.x;
    int i = blockIdx.x * SB + t;
    sh[t] = (i < N_NODES) ? g_indeg[i] : 0;
    __syncthreads();
#pragma unroll
    for (int off = SB / 2; off > 0; off >>= 1) {
        if (t < off) sh[t] += sh[t + off];
        __syncthreads();
    }
    if (t == 0) g_blocksum[blockIdx.x] = sh[0];
}

__global__ void __launch_bounds__(256) blockscan_kernel() {
    __shared__ int sh[256];
    int t = threadIdx.x;
    int v = (t < NSB) ? g_blocksum[t] : 0;
    sh[t] = v;
    __syncthreads();
#pragma unroll
    for (int off = 1; off < 256; off <<= 1) {
        int u = (t >= off) ? sh[t - off] : 0;
        __syncthreads();
        sh[t] += u;
        __syncthreads();
    }
    g_blockoff[t] = sh[t] - v;
}

__global__ void __launch_bounds__(SB) offsets_kernel() {
    __shared__ int sh[SB];
    int t = threadIdx.x;
    int i = blockIdx.x * SB + t;
    int v = (i < N_NODES) ? g_indeg[i] : 0;
    sh[t] = v;
    __syncthreads();
#pragma unroll
    for (int off = 1; off < SB; off <<= 1) {
        int u = (t >= off) ? sh[t - off] : 0;
        __syncthreads();
        sh[t] += u;
        __syncthreads();
    }
    if (i < N_NODES) {
        int o = g_blockoff[blockIdx.x] + sh[t] - v;
        g_off[i] = o;
        g_cur[i] = o;
    }
}

__global__ void scatter_kernel(const int* __restrict__ src, const int* __restrict__ dst) {
    int e = blockIdx.x * blockDim.x + threadIdx.x;
    if (e < N_EDGES) {
        int p = atomicAdd(&g_cur[dst[e]], 1);
        g_col[p] = src[e];
    }
}

// ---------------- aggregation ----------------
__global__ void __launch_bounds__(128) agg_kernel(const float* __restrict__ hin,
                                                  float* __restrict__ hout) {
    int node = blockIdx.x;
    int c    = threadIdx.x;
    float acc = hin[node * D + c] * g_nsrc[node];
    int beg = g_off[node];
    int cnt = g_indeg[node];
    int k = 0;
    for (; k + 4 <= cnt; k += 4) {
        int s0 = __ldg(&g_col[beg + k + 0]);
        int s1 = __ldg(&g_col[beg + k + 1]);
        int s2 = __ldg(&g_col[beg + k + 2]);
        int s3 = __ldg(&g_col[beg + k + 3]);
        float n0 = __ldg(&g_nsrc[s0]);
        float n1 = __ldg(&g_nsrc[s1]);
        float n2 = __ldg(&g_nsrc[s2]);
        float n3 = __ldg(&g_nsrc[s3]);
        float v0 = __ldg(&hin[s0 * D + c]);
        float v1 = __ldg(&hin[s1 * D + c]);
        float v2 = __ldg(&hin[s2 * D + c]);
        float v3 = __ldg(&hin[s3 * D + c]);
        acc += n0 * v0;
        acc += n1 * v1;
        acc += n2 * v2;
        acc += n3 * v3;
    }
    for (; k < cnt; k++) {
        int s = __ldg(&g_col[beg + k]);
        acc += __ldg(&g_nsrc[s]) * __ldg(&hin[s * D + c]);
    }
    hout[node * D + c] = acc * g_ndst[node];
}

// ---------------- tf32 mma.sync GEMM (3xTF32 split) ----------------
// out[node][n] = sum_k M[node][k] * W[k][n] (+ fused bias / BN / leaky)
// Persistent 148 blocks x 256 thr. Tile 128x128, warp grid 2x4 (64x32/warp).
// W staged hi/lo once per block (pad 136: B-frag banks 8s+q -> conflict-free).
// A staged raw per tile (pad 132: A-frag banks 4q+s -> conflict-free).
#define NT_TILES ((N_NODES + 127) / 128)   // 782
#define APAD 132
#define BPAD 136

#define AS_OFF 0
#define AS_BYTES (128 * APAD * 4)                 // 67584
#define BH_OFF (AS_OFF + AS_BYTES)
#define BB_BYTES (128 * BPAD * 4)                 // 69632
#define BL_OFF (BH_OFF + BB_BYTES)
#define SC_OFF (BL_OFF + BB_BYTES)
#define SH_OFF (SC_OFF + 512)
#define SMEM_TOTAL_MMA (SH_OFF + 512)             // 207872

#define F2TF32(d, f) asm("cvt.rna.tf32.f32 %0, %1;" : "=r"(d) : "f"(f))

__device__ __forceinline__ void mma_tf32(float* c, uint32_t a0, uint32_t a1,
                                         uint32_t a2, uint32_t a3,
                                         uint32_t b0, uint32_t b1) {
    asm volatile(
        "mma.sync.aligned.m16n8k8.row.col.f32.tf32.tf32.f32 "
        "{%0,%1,%2,%3}, {%4,%5,%6,%7}, {%8,%9}, {%0,%1,%2,%3};"
        : "+f"(c[0]), "+f"(c[1]), "+f"(c[2]), "+f"(c[3])
        : "r"(a0), "r"(a1), "r"(a2), "r"(a3), "r"(b0), "r"(b1));
}

template <bool FUSE_BN>
__global__ void __launch_bounds__(256) mma_gemm_kernel(
    const float* __restrict__ Min, const float* __restrict__ W,
    const float* __restrict__ bias,
    const float* __restrict__ gamma, const float* __restrict__ beta,
    const float* __restrict__ mean,  const float* __restrict__ var,
    float* __restrict__ out) {
    extern __shared__ char smem[];
    float* As = (float*)(smem + AS_OFF);
    float* Bh = (float*)(smem + BH_OFF);
    float* Bl = (float*)(smem + BL_OFF);
    float* Sc = (float*)(smem + SC_OFF);
    float* Sh = (float*)(smem + SH_OFF);

    int t    = threadIdx.x;
    int wid  = t >> 5;
    int lane = t & 31;
    int q    = lane >> 2;   // group id
    int s    = lane & 3;    // thread-in-group

    // epilogue constants per output column
    if (t < D) {
        float scv, shv;
        if (FUSE_BN) {
            float isd = rsqrtf(var[t] + BN_EPS);
            scv = gamma[t] * isd;
            shv = (bias[t] - mean[t]) * scv + beta[t];
        } else {
            scv = 1.0f;
            shv = bias[t];
        }
        Sc[t] = scv;
        Sh[t] = shv;
    }

    // stage B = W (k-major) hi/lo once per block
    for (int i = t; i < D * D; i += 256) {
        int k = i >> 7, n = i & 127;
        float a = W[i];
        uint32_t hb; F2TF32(hb, a);
        float lo = a - __uint_as_float(hb);
        uint32_t lb; F2TF32(lb, lo);
        Bh[k * BPAD + n] = __uint_as_float(hb);
        Bl[k * BPAD + n] = __uint_as_float(lb);
    }
    __syncthreads();

    int wr = wid >> 2;          // warp row (0..1): rows wr*64..wr*64+63
    int wc = wid & 3;           // warp col (0..3): cols wc*32..wc*32+31

    for (int tile = blockIdx.x; tile < NT_TILES; tile += gridDim.x) {
        // stage A tile (128 rows x 128 cols) raw fp32, zero-pad tail rows
        for (int i = t; i < 128 * 32; i += 256) {     // float4 index
            int r = i >> 5, c4 = i & 31;
            int node = tile * 128 + r;
            float4 v = (node < N_NODES)
                     ? __ldg((const float4*)(Min + (size_t)node * D) + c4)
                     : make_float4(0.f, 0.f, 0.f, 0.f);
            *(float4*)&As[r * APAD + c4 * 4] = v;
        }
        __syncthreads();

        float acc[4][4][4];
#pragma unroll
        for (int mt = 0; mt < 4; mt++)
#pragma unroll
            for (int nt = 0; nt < 4; nt++)
#pragma unroll
                for (int i = 0; i < 4; i++) acc[mt][nt][i] = 0.f;

#pragma unroll 2
        for (int k0 = 0; k0 < D; k0 += 8) {
            uint32_t ahi[4][4], alo[4][4];
#pragma unroll
            for (int mt = 0; mt < 4; mt++) {
                int rb = wr * 64 + mt * 16 + q;
                float a0 = As[rb * APAD + k0 + s];
                float a1 = As[(rb + 8) * APAD + k0 + s];
                float a2 = As[rb * APAD + k0 + s + 4];
                float a3 = As[(rb + 8) * APAD + k0 + s + 4];
                F2TF32(ahi[mt][0], a0); F2TF32(ahi[mt][1], a1);
                F2TF32(ahi[mt][2], a2); F2TF32(ahi[mt][3], a3);
                float l0 = a0 - __uint_as_float(ahi[mt][0]);
                float l1 = a1 - __uint_as_float(ahi[mt][1]);
                float l2 = a2 - __uint_as_float(ahi[mt][2]);
                float l3 = a3 - __uint_as_float(ahi[mt][3]);
                F2TF32(alo[mt][0], l0); F2TF32(alo[mt][1], l1);
                F2TF32(alo[mt][2], l2); F2TF32(alo[mt][3], l3);
            }
#pragma unroll
            for (int nt = 0; nt < 4; nt++) {
                int nb = wc * 32 + nt * 8 + q;
                uint32_t bh0 = __float_as_uint(Bh[(k0 + s) * BPAD + nb]);
                uint32_t bh1 = __float_as_uint(Bh[(k0 + s + 4) * BPAD + nb]);
                uint32_t bl0 = __float_as_uint(Bl[(k0 + s) * BPAD + nb]);
                uint32_t bl1 = __float_as_uint(Bl[(k0 + s + 4) * BPAD + nb]);
#pragma unroll
                for (int mt = 0; mt < 4; mt++) {
                    mma_tf32(acc[mt][nt], ahi[mt][0], ahi[mt][1], ahi[mt][2], ahi[mt][3], bh0, bh1);
                    mma_tf32(acc[mt][nt], ahi[mt][0], ahi[mt][1], ahi[mt][2], ahi[mt][3], bl0, bl1);
                    mma_tf32(acc[mt][nt], alo[mt][0], alo[mt][1], alo[mt][2], alo[mt][3], bh0, bh1);
                }
            }
        }

        // epilogue: c0,c1 -> (row q, cols 2s,2s+1); c2,c3 -> row q+8
#pragma unroll
        for (int mt = 0; mt < 4; mt++) {
            int row0 = tile * 128 + wr * 64 + mt * 16 + q;
#pragma unroll
            for (int nt = 0; nt < 4; nt++) {
                int col = wc * 32 + nt * 8 + 2 * s;
                float scx = Sc[col], scy = Sc[col + 1];
                float shx = Sh[col], shy = Sh[col + 1];
                float vx = acc[mt][nt][0] * scx + shx;
                float vy = acc[mt][nt][1] * scy + shy;
                float wx = acc[mt][nt][2] * scx + shx;
                float wy = acc[mt][nt][3] * scy + shy;
                if (FUSE_BN) {
                    vx = vx > 0.f ? vx : LEAKY * vx;
                    vy = vy > 0.f ? vy : LEAKY * vy;
                    wx = wx > 0.f ? wx : LEAKY * wx;
                    wy = wy > 0.f ? wy : LEAKY * wy;
                }
                if (row0 < N_NODES)
                    *(float2*)&out[(size_t)row0 * D + col] = make_float2(vx, vy);
                if (row0 + 8 < N_NODES)
                    *(float2*)&out[(size_t)(row0 + 8) * D + col] = make_float2(wx, wy);
            }
        }
        __syncthreads();
    }
}

// ---------------- launch ----------------
extern "C" void kernel_launch(void* const* d_in, const int* in_sizes, int n_in,
                              void* d_out, int out_size) {
    const float* x     = (const float*)d_in[0];
    const int*   src   = (const int*)  d_in[1];
    const int*   dst   = (const int*)  d_in[2];
    const float* W1    = (const float*)d_in[3];
    const float* b1    = (const float*)d_in[4];
    const float* W2    = (const float*)d_in[5];
    const float* b2    = (const float*)d_in[6];
    const float* gamma = (const float*)d_in[7];
    const float* beta  = (const float*)d_in[8];
    const float* rmean = (const float*)d_in[9];
    const float* rvar  = (const float*)d_in[10];
    float* out = (float*)d_out;

    cudaFuncSetAttribute(mma_gemm_kernel<true>,
                         cudaFuncAttributeMaxDynamicSharedMemorySize, SMEM_TOTAL_MMA);
    cudaFuncSetAttribute(mma_gemm_kernel<false>,
                         cudaFuncAttributeMaxDynamicSharedMemorySize, SMEM_TOTAL_MMA);

    float* d_m = nullptr;
    float* d_h = nullptr;
    cudaGetSymbolAddress((void**)&d_m, g_m);
    cudaGetSymbolAddress((void**)&d_h, g_h);

    const int nodeGrid = (N_NODES + 255) / 256;
    const int edgeGrid = (N_EDGES + 255) / 256;

    // graph prep (rebuilt every replay)
    zero_deg_kernel<<<nodeGrid, 256>>>();
    degree_kernel<<<edgeGrid, 256>>>(src, dst);
    norm_kernel<<<nodeGrid, 256>>>();
    blocksum_kernel<<<NSB, SB>>>();
    blockscan_kernel<<<1, 256>>>();
    offsets_kernel<<<NSB, SB>>>();
    scatter_kernel<<<edgeGrid, 256>>>(src, dst);

    // layer 0: conv -> BN(eval) -> leaky
    agg_kernel<<<N_NODES, 128>>>(x, d_m);
    mma_gemm_kernel<true><<<148, 256, SMEM_TOTAL_MMA>>>(d_m, W1, b1, gamma, beta,
                                                        rmean, rvar, d_h);

    // layer 1: conv only
    agg_kernel<<<N_NODES, 128>>>(d_h, d_m);
    mma_gemm_kernel<false><<<148, 256, SMEM_TOTAL_MMA>>>(d_m, W2, b2, nullptr, nullptr,
                                                         nullptr, nullptr, out);
}